// round 3
// baseline (speedup 1.0000x reference)
#include <cuda_runtime.h>
#include <cuda_bf16.h>
#include <math.h>

// Problem constants (fixed shapes)
#define BB       32
#define DIM      4096
#define HQ       32
#define HKV      8
#define REP      4
#define HD       128
#define MAXS     2048
#define STARTP   2047
#define NQKV     6144            // HQ*HD + 2*HKV*HD
#define TLEN     2048            // STARTP + 1

// GEMM config
#define GEMM_NT  64
#define GEMM_KC  32
#define KSPLIT   4

// Attention config
#define NSPLIT   16
#define CHUNK    128             // TLEN / NSPLIT
#define PPW      16              // positions per warp (8 warps * 16 = 128)

// ---------------- scratch (device globals; no allocation allowed) ----------------
__device__ float g_p1[KSPLIT * BB * NQKV];            // qkv split-K partials (3 MB)
__device__ float g_qkv[BB * NQKV];                    // fused q|k|v after rope (768 KB)
__device__ float g_pacc[BB * HKV * NSPLIT * REP * HD];// attn split partials (8 MB)
__device__ float g_pml[BB * HKV * NSPLIT * 5];        // (m, l0..l3) per split
__device__ float g_attn[BB * HQ * HD];                // attention output (512 KB)
__device__ float g_p2[KSPLIT * BB * DIM];             // out-proj split-K partials (2 MB)

// ---------------- GEMM: y[b,n] = sum_k x[b,k] * w[n,k], split-K partials ----------
// grid: (N/64, KSPLIT), block: 256.
// Weight row n selects w0 for n<4096, w1 for 4096<=n<5120, w2 for n>=5120
// (for the output projection pass w0=w1=w2=wo; N=4096 so only w0 is used).
__global__ __launch_bounds__(256) void gemm_splitk(
    const float* __restrict__ x,
    const float* __restrict__ w0,
    const float* __restrict__ w1,
    const float* __restrict__ w2,
    float* __restrict__ part,
    int N, int K, int KLEN)
{
    __shared__ float xs[GEMM_KC][34];           // [k][b]  (+2 pad keeps float2 aligned)
    __shared__ float ws[GEMM_KC][GEMM_NT + 4];  // [k][n]  (+4 pad keeps float4 aligned)

    const int n0    = blockIdx.x * GEMM_NT;
    const int kbase = blockIdx.y * KLEN;
    const int t     = threadIdx.x;

    const float* w;
    int nrel;
    if (n0 < 4096)      { w = w0; nrel = n0; }
    else if (n0 < 5120) { w = w1; nrel = n0 - 4096; }
    else                { w = w2; nrel = n0 - 5120; }

    const int ng = t & 15;   // 16 groups * 4 n
    const int bg = t >> 4;   // 16 groups * 2 b

    float acc[4][2] = {};

    for (int k0 = 0; k0 < KLEN; k0 += GEMM_KC) {
        // x chunk: 32 b x 32 k = 1024 floats -> one float4 per thread
        {
            int b  = t >> 3;
            int kk = (t & 7) << 2;
            float4 v = *(const float4*)(x + (size_t)b * K + kbase + k0 + kk);
            xs[kk + 0][b] = v.x; xs[kk + 1][b] = v.y;
            xs[kk + 2][b] = v.z; xs[kk + 3][b] = v.w;
        }
        // w chunk: 64 n x 32 k = 2048 floats -> two float4 per thread
        #pragma unroll
        for (int i = 0; i < 2; i++) {
            int idx = t + (i << 8);
            int n   = idx >> 3;
            int kk  = (idx & 7) << 2;
            float4 v = *(const float4*)(w + (size_t)(nrel + n) * K + kbase + k0 + kk);
            ws[kk + 0][n] = v.x; ws[kk + 1][n] = v.y;
            ws[kk + 2][n] = v.z; ws[kk + 3][n] = v.w;
        }
        __syncthreads();
        #pragma unroll
        for (int k = 0; k < GEMM_KC; k++) {
            float4 wv = *(const float4*)&ws[k][ng * 4];
            float2 xv = *(const float2*)&xs[k][bg * 2];
            acc[0][0] += wv.x * xv.x; acc[0][1] += wv.x * xv.y;
            acc[1][0] += wv.y * xv.x; acc[1][1] += wv.y * xv.y;
            acc[2][0] += wv.z * xv.x; acc[2][1] += wv.z * xv.y;
            acc[3][0] += wv.w * xv.x; acc[3][1] += wv.w * xv.y;
        }
        __syncthreads();
    }

    float* dst = part + ((size_t)blockIdx.y * BB + bg * 2) * N + n0 + ng * 4;
    float4 r0 = make_float4(acc[0][0], acc[1][0], acc[2][0], acc[3][0]);
    float4 r1 = make_float4(acc[0][1], acc[1][1], acc[2][1], acc[3][1]);
    *(float4*)dst       = r0;
    *(float4*)(dst + N) = r1;
}

// ------------- reduce split-K partials of QKV and apply RoPE in one pass ----------
// one thread per pair (2 consecutive features). total pairs = 32 * 3072.
__global__ __launch_bounds__(256) void reduce_rope(
    const float* __restrict__ part,
    float* __restrict__ qkv,
    const float* __restrict__ fcos,
    const float* __restrict__ fsin)
{
    int idx = blockIdx.x * 256 + threadIdx.x;
    if (idx >= BB * (NQKV / 2)) return;
    int b  = idx / (NQKV / 2);
    int n0 = (idx - b * (NQKV / 2)) * 2;

    float a0 = 0.f, a1 = 0.f;
    #pragma unroll
    for (int s = 0; s < KSPLIT; s++) {
        const float* p = part + ((size_t)s * BB + b) * NQKV + n0;
        a0 += p[0];
        a1 += p[1];
    }
    if (n0 < 5120) {   // q (0..4095) and k (4096..5119) get RoPE; v does not
        int d = n0 & (HD - 1);
        int p = d >> 1;
        float c = fcos[p], s = fsin[p];
        float r0 = a0 * c - a1 * s;
        float r1 = a0 * s + a1 * c;
        a0 = r0; a1 = r1;
    }
    float* dst = qkv + (size_t)b * NQKV + n0;
    dst[0] = a0;
    dst[1] = a1;
}

// ---------------- flash-decode attention, split over KV positions ----------------
// grid: (NSPLIT, HKV, B), block: 256 (8 warps * 16 positions = 128-position chunk)
// Per-warp state: shared running max m (valid upper bound across the 4 heads of the
// group), but PER-HEAD denominators l[4] — normalization is per head.
__global__ __launch_bounds__(256) void attn_kernel(
    const float* __restrict__ qkv,
    const float* __restrict__ kc,
    const float* __restrict__ vc,
    float* __restrict__ pacc,
    float* __restrict__ pml)
{
    const int split = blockIdx.x;
    const int g     = blockIdx.y;
    const int b     = blockIdx.z;
    const int t     = threadIdx.x;
    const int warp  = t >> 5, lane = t & 31;

    __shared__ float s_acc[8][REP][HD];   // 16 KB
    __shared__ float s_m[8], s_l[8][REP], s_alpha[8];
    __shared__ float s_ML[1 + REP];       // block (m, l0..l3)

    const float scale = 0.08838834764831845f;  // 1/sqrt(128)

    // q for the 4 heads of this group, pre-scaled, in registers (4 floats/lane/head)
    float4 qr[REP];
    #pragma unroll
    for (int r = 0; r < REP; r++) {
        const float* qp = qkv + (size_t)b * NQKV + (g * REP + r) * HD + lane * 4;
        float4 v = *(const float4*)qp;
        qr[r] = make_float4(v.x * scale, v.y * scale, v.z * scale, v.w * scale);
    }
    const float* knew = qkv + (size_t)b * NQKV + 4096 + g * HD;
    const float* vnew = qkv + (size_t)b * NQKV + 5120 + g * HD;

    float m = -1e30f;
    float l0 = 0.f, l1 = 0.f, l2 = 0.f, l3 = 0.f;
    float4 oa[REP];
    #pragma unroll
    for (int r = 0; r < REP; r++) oa[r] = make_float4(0.f, 0.f, 0.f, 0.f);

    const int tbase = split * CHUNK + warp * PPW;
    for (int i = 0; i < PPW; i++) {
        const int tp = tbase + i;
        const float* kp;
        const float* vp;
        if (tp < STARTP) {
            size_t off = ((size_t)(b * MAXS + tp) * HKV + g) * HD;
            kp = kc + off;
            vp = vc + off;
        } else {
            kp = knew;
            vp = vnew;
        }
        float4 kv = *(const float4*)(kp + lane * 4);
        float4 vv = *(const float4*)(vp + lane * 4);

        float sc0 = kv.x*qr[0].x + kv.y*qr[0].y + kv.z*qr[0].z + kv.w*qr[0].w;
        float sc1 = kv.x*qr[1].x + kv.y*qr[1].y + kv.z*qr[1].z + kv.w*qr[1].w;
        float sc2 = kv.x*qr[2].x + kv.y*qr[2].y + kv.z*qr[2].z + kv.w*qr[2].w;
        float sc3 = kv.x*qr[3].x + kv.y*qr[3].y + kv.z*qr[3].z + kv.w*qr[3].w;
        #pragma unroll
        for (int off = 16; off > 0; off >>= 1) {
            sc0 += __shfl_xor_sync(0xffffffffu, sc0, off);
            sc1 += __shfl_xor_sync(0xffffffffu, sc1, off);
            sc2 += __shfl_xor_sync(0xffffffffu, sc2, off);
            sc3 += __shfl_xor_sync(0xffffffffu, sc3, off);
        }
        float mnew = fmaxf(fmaxf(fmaxf(sc0, sc1), fmaxf(sc2, sc3)), m);
        float corr = __expf(m - mnew);
        float p0 = __expf(sc0 - mnew);
        float p1 = __expf(sc1 - mnew);
        float p2 = __expf(sc2 - mnew);
        float p3 = __expf(sc3 - mnew);
        l0 = l0 * corr + p0;
        l1 = l1 * corr + p1;
        l2 = l2 * corr + p2;
        l3 = l3 * corr + p3;
        oa[0].x = oa[0].x*corr + p0*vv.x; oa[0].y = oa[0].y*corr + p0*vv.y;
        oa[0].z = oa[0].z*corr + p0*vv.z; oa[0].w = oa[0].w*corr + p0*vv.w;
        oa[1].x = oa[1].x*corr + p1*vv.x; oa[1].y = oa[1].y*corr + p1*vv.y;
        oa[1].z = oa[1].z*corr + p1*vv.z; oa[1].w = oa[1].w*corr + p1*vv.w;
        oa[2].x = oa[2].x*corr + p2*vv.x; oa[2].y = oa[2].y*corr + p2*vv.y;
        oa[2].z = oa[2].z*corr + p2*vv.z; oa[2].w = oa[2].w*corr + p2*vv.w;
        oa[3].x = oa[3].x*corr + p3*vv.x; oa[3].y = oa[3].y*corr + p3*vv.y;
        oa[3].z = oa[3].z*corr + p3*vv.z; oa[3].w = oa[3].w*corr + p3*vv.w;
        m = mnew;
    }

    if (lane == 0) {
        s_m[warp] = m;
        s_l[warp][0] = l0; s_l[warp][1] = l1;
        s_l[warp][2] = l2; s_l[warp][3] = l3;
    }
    #pragma unroll
    for (int r = 0; r < REP; r++)
        *(float4*)&s_acc[warp][r][lane * 4] = oa[r];
    __syncthreads();

    if (t == 0) {
        float M = s_m[0];
        #pragma unroll
        for (int w = 1; w < 8; w++) M = fmaxf(M, s_m[w]);
        float L[REP] = {0.f, 0.f, 0.f, 0.f};
        #pragma unroll
        for (int w = 0; w < 8; w++) {
            float a = __expf(s_m[w] - M);
            s_alpha[w] = a;
            #pragma unroll
            for (int r = 0; r < REP; r++) L[r] += a * s_l[w][r];
        }
        s_ML[0] = M;
        #pragma unroll
        for (int r = 0; r < REP; r++) s_ML[1 + r] = L[r];
    }
    __syncthreads();

    const size_t base = ((size_t)(b * HKV + g) * NSPLIT + split) * (REP * HD);
    for (int o = t; o < REP * HD; o += 256) {
        int r = o >> 7, d = o & (HD - 1);
        float sum = 0.f;
        #pragma unroll
        for (int w = 0; w < 8; w++) sum += s_alpha[w] * s_acc[w][r][d];
        pacc[base + o] = sum;
    }
    if (t < 1 + REP) {
        size_t mlb = ((size_t)(b * HKV + g) * NSPLIT + split) * 5;
        pml[mlb + t] = s_ML[t];
    }
}

// ---------------- combine KV splits into the final attention output ---------------
// grid: (HKV, B), block: 256
__global__ __launch_bounds__(256) void attn_reduce(
    const float* __restrict__ pacc,
    const float* __restrict__ pml,
    float* __restrict__ attn)
{
    const int g = blockIdx.x, b = blockIdx.y;
    const int t = threadIdx.x;
    __shared__ float alpha[NSPLIT];
    __shared__ float s_inv[REP];

    const int bg = b * HKV + g;
    if (t == 0) {
        float M = -1e30f;
        #pragma unroll
        for (int i = 0; i < NSPLIT; i++)
            M = fmaxf(M, pml[((size_t)bg * NSPLIT + i) * 5]);
        float L[REP] = {0.f, 0.f, 0.f, 0.f};
        #pragma unroll
        for (int i = 0; i < NSPLIT; i++) {
            const float* ml = pml + ((size_t)bg * NSPLIT + i) * 5;
            float a = __expf(ml[0] - M);
            alpha[i] = a;
            #pragma unroll
            for (int r = 0; r < REP; r++) L[r] += a * ml[1 + r];
        }
        #pragma unroll
        for (int r = 0; r < REP; r++) s_inv[r] = 1.0f / L[r];
    }
    __syncthreads();

    for (int o = t; o < REP * HD; o += 256) {
        int r = o >> 7;
        float sum = 0.f;
        #pragma unroll
        for (int i = 0; i < NSPLIT; i++)
            sum += alpha[i] * pacc[((size_t)bg * NSPLIT + i) * (REP * HD) + o];
        attn[(size_t)b * (HQ * HD) + g * (REP * HD) + o] = sum * s_inv[r];
    }
}

// ---------------- sum split-K partials of the output projection -------------------
__global__ __launch_bounds__(256) void reduce_out(
    const float* __restrict__ part, float* __restrict__ out, int total)
{
    int idx = blockIdx.x * 256 + threadIdx.x;
    if (idx >= total) return;
    float a = part[idx];
    #pragma unroll
    for (int s = 1; s < KSPLIT; s++) a += part[(size_t)s * total + idx];
    out[idx] = a;
}

// ------------------------------------ launch --------------------------------------
extern "C" void kernel_launch(void* const* d_in, const int* in_sizes, int n_in,
                              void* d_out, int out_size)
{
    const float* x  = (const float*)d_in[0];
    const float* fc = (const float*)d_in[1];
    const float* fs = (const float*)d_in[2];
    const float* wq = (const float*)d_in[3];
    const float* wk = (const float*)d_in[4];
    const float* wv = (const float*)d_in[5];
    const float* wo = (const float*)d_in[6];
    const float* kc = (const float*)d_in[7];
    const float* vc = (const float*)d_in[8];
    float* out = (float*)d_out;

    void *p1, *pqkv, *pacc, *pml, *pattn, *p2;
    cudaGetSymbolAddress(&p1,   g_p1);
    cudaGetSymbolAddress(&pqkv, g_qkv);
    cudaGetSymbolAddress(&pacc, g_pacc);
    cudaGetSymbolAddress(&pml,  g_pml);
    cudaGetSymbolAddress(&pattn,g_attn);
    cudaGetSymbolAddress(&p2,   g_p2);

    // 1) fused QKV projection, split-K
    gemm_splitk<<<dim3(NQKV / GEMM_NT, KSPLIT), 256>>>(
        x, wq, wk, wv, (float*)p1, NQKV, DIM, DIM / KSPLIT);

    // 2) reduce partials + RoPE
    reduce_rope<<<(BB * (NQKV / 2) + 255) / 256, 256>>>(
        (const float*)p1, (float*)pqkv, fc, fs);

    // 3) flash-decode attention over KV splits
    attn_kernel<<<dim3(NSPLIT, HKV, BB), 256>>>(
        (const float*)pqkv, kc, vc, (float*)pacc, (float*)pml);

    // 4) combine splits
    attn_reduce<<<dim3(HKV, BB), 256>>>(
        (const float*)pacc, (const float*)pml, (float*)pattn);

    // 5) output projection, split-K
    gemm_splitk<<<dim3(DIM / GEMM_NT, KSPLIT), 256>>>(
        (const float*)pattn, wo, wo, wo, (float*)p2, DIM, HQ * HD, DIM / KSPLIT);

    // 6) reduce into d_out
    reduce_out<<<(BB * DIM + 255) / 256, 256>>>((const float*)p2, out, BB * DIM);
}

// round 4
// speedup vs baseline: 1.3255x; 1.3255x over previous
#include <cuda_runtime.h>
#include <cuda_bf16.h>
#include <math.h>

// Problem constants (fixed shapes)
#define BB       32
#define DIM      4096
#define HQ       32
#define HKV      8
#define REP      4
#define HD       128
#define MAXS     2048
#define STARTP   2047
#define NQKV     6144            // HQ*HD + 2*HKV*HD

// GEMM config
#define NT       512             // n per block
#define KC       8               // k per smem chunk
#define WSS      516             // ws row stride (floats): 4-row offset = 16 banks -> conflict-free stores
#define XSS      36              // xs row stride
#define KSPLIT   32              // both GEMMs

// Attention config
#define NSPLIT   16
#define CHUNK    128             // TLEN / NSPLIT
#define PPW      16              // positions per warp (8 warps * 16 = 128)

// ---------------- scratch (device globals; no allocation allowed) ----------------
__device__ float g_p1[KSPLIT * BB * NQKV];            // qkv split-K partials (25 MB)
__device__ float g_qkv[BB * NQKV];                    // fused q|k|v after rope (768 KB)
__device__ float g_pacc[BB * HKV * NSPLIT * REP * HD];// attn split partials (8 MB)
__device__ float g_pml[BB * HKV * NSPLIT * 5];        // (m, l0..l3) per split
__device__ float g_attn[BB * HQ * HD];                // attention output (512 KB)
__device__ float g_p2[KSPLIT * BB * DIM];             // out-proj split-K partials (17 MB)

#define FMA2(acc, a, b) asm("fma.rn.f32x2 %0, %1, %2, %0;" : "+l"(acc) : "l"(a), "l"(b))

// ---------------- GEMM: y[b,n] = sum_k x[b,k] * w[n,k], split-K partials ----------
// grid: (N/512, KSPLIT), block 256.  Per-thread tile 8n x 8b, b paired into f32x2.
// Weight row n selects w0 for n<4096, w1 for 4096<=n<5120, w2 for n>=5120.
__global__ __launch_bounds__(256) void gemm_f32x2(
    const float* __restrict__ x,
    const float* __restrict__ w0,
    const float* __restrict__ w1,
    const float* __restrict__ w2,
    float* __restrict__ part,
    int N, int K, int KLEN)
{
    __shared__ __align__(16) float ws[KC][WSS];   // [k][n] 16.5 KB
    __shared__ __align__(16) float xs[KC][XSS];   // [k][b] 1.2 KB

    const int n0    = blockIdx.x * NT;
    const int kbase = blockIdx.y * KLEN;
    const int t     = threadIdx.x;
    const int ng    = t & 63;     // 64 groups * 8 n
    const int bg    = t >> 6;     // 4 groups * 8 b

    const float* w;
    int nrel;
    if (n0 < 4096)      { w = w0; nrel = n0; }
    else if (n0 < 5120) { w = w1; nrel = n0 - 4096; }
    else                { w = w2; nrel = n0 - 5120; }

    // load/staging identities: w tile 512 rows x 8 k = 1024 float4, 4 per thread
    const int wrow = t >> 1;          // + i*128
    const int kc0  = (t & 1) * 4;     // k-offset of the float4 within the chunk
    const float* wbase = w + (size_t)(nrel + wrow) * K + kbase + kc0;
    const float* xbase = x + (size_t)(t >> 1) * K + kbase + kc0;  // t<64 only

    unsigned long long acc[8][4] = {};   // [n][b-pair]
    float4 wst[4];
    float4 xst;

    const int nch = KLEN / KC;

    // initial stage load (chunk 0)
    #pragma unroll
    for (int i = 0; i < 4; i++) wst[i] = *(const float4*)(wbase + (size_t)i * 128 * K);
    if (t < 64) xst = *(const float4*)xbase;

    for (int ck = 0; ck < nch; ck++) {
        // stage -> smem (transposed to [k][n] / [k][b])
        #pragma unroll
        for (int i = 0; i < 4; i++) {
            int n = wrow + i * 128;
            ws[kc0 + 0][n] = wst[i].x; ws[kc0 + 1][n] = wst[i].y;
            ws[kc0 + 2][n] = wst[i].z; ws[kc0 + 3][n] = wst[i].w;
        }
        if (t < 64) {
            int b = t >> 1;
            xs[kc0 + 0][b] = xst.x; xs[kc0 + 1][b] = xst.y;
            xs[kc0 + 2][b] = xst.z; xs[kc0 + 3][b] = xst.w;
        }
        __syncthreads();

        // prefetch next chunk into registers while computing this one
        if (ck + 1 < nch) {
            int ko = (ck + 1) * KC;
            #pragma unroll
            for (int i = 0; i < 4; i++)
                wst[i] = *(const float4*)(wbase + ko + (size_t)i * 128 * K);
            if (t < 64) xst = *(const float4*)(xbase + ko);
        }

        #pragma unroll
        for (int k = 0; k < KC; k++) {
            float4 wA = *(const float4*)&ws[k][ng * 8];
            float4 wB = *(const float4*)&ws[k][ng * 8 + 4];
            double2 x01 = *(const double2*)&xs[k][bg * 8];
            double2 x23 = *(const double2*)&xs[k][bg * 8 + 4];
            unsigned long long xp[4];
            xp[0] = __double_as_longlong(x01.x);
            xp[1] = __double_as_longlong(x01.y);
            xp[2] = __double_as_longlong(x23.x);
            xp[3] = __double_as_longlong(x23.y);
            float wv[8] = {wA.x, wA.y, wA.z, wA.w, wB.x, wB.y, wB.z, wB.w};
            #pragma unroll
            for (int i = 0; i < 8; i++) {
                unsigned long long wp;
                asm("mov.b64 %0, {%1, %1};" : "=l"(wp) : "f"(wv[i]));
                #pragma unroll
                for (int j = 0; j < 4; j++) FMA2(acc[i][j], wp, xp[j]);
            }
        }
        __syncthreads();
    }

    // epilogue: part[split][b][n]
    float* dst = part + ((size_t)blockIdx.y * BB + bg * 8) * N + n0 + ng * 8;
    #pragma unroll
    for (int j = 0; j < 4; j++) {          // b pair j -> rows bg*8+2j, +1
        float lo[8], hi[8];
        #pragma unroll
        for (int i = 0; i < 8; i++)
            asm("mov.b64 {%0, %1}, %2;" : "=f"(lo[i]), "=f"(hi[i]) : "l"(acc[i][j]));
        float* d0 = dst + (size_t)(2 * j) * N;
        float* d1 = d0 + N;
        *(float4*)(d0)     = make_float4(lo[0], lo[1], lo[2], lo[3]);
        *(float4*)(d0 + 4) = make_float4(lo[4], lo[5], lo[6], lo[7]);
        *(float4*)(d1)     = make_float4(hi[0], hi[1], hi[2], hi[3]);
        *(float4*)(d1 + 4) = make_float4(hi[4], hi[5], hi[6], hi[7]);
    }
}

// ------------- reduce split-K partials of QKV and apply RoPE in one pass ----------
__global__ __launch_bounds__(256) void reduce_rope(
    const float* __restrict__ part,
    float* __restrict__ qkv,
    const float* __restrict__ fcos,
    const float* __restrict__ fsin)
{
    int idx = blockIdx.x * 256 + threadIdx.x;
    if (idx >= BB * (NQKV / 2)) return;
    int b  = idx / (NQKV / 2);
    int n0 = (idx - b * (NQKV / 2)) * 2;

    float a0 = 0.f, a1 = 0.f;
    #pragma unroll 8
    for (int s = 0; s < KSPLIT; s++) {
        const float* p = part + ((size_t)s * BB + b) * NQKV + n0;
        a0 += p[0];
        a1 += p[1];
    }
    if (n0 < 5120) {   // q (0..4095) and k (4096..5119) get RoPE; v does not
        int d = n0 & (HD - 1);
        int p = d >> 1;
        float c = fcos[p], s = fsin[p];
        float r0 = a0 * c - a1 * s;
        float r1 = a0 * s + a1 * c;
        a0 = r0; a1 = r1;
    }
    float* dst = qkv + (size_t)b * NQKV + n0;
    dst[0] = a0;
    dst[1] = a1;
}

// ---------------- flash-decode attention, split over KV positions ----------------
// grid: (NSPLIT, HKV, B), block 256 (8 warps * 16 positions).  Shared running max m
// across the 4 GQA heads (stability shift only), per-head denominators l0..l3.
__global__ __launch_bounds__(256) void attn_kernel(
    const float* __restrict__ qkv,
    const float* __restrict__ kc,
    const float* __restrict__ vc,
    float* __restrict__ pacc,
    float* __restrict__ pml)
{
    const int split = blockIdx.x;
    const int g     = blockIdx.y;
    const int b     = blockIdx.z;
    const int t     = threadIdx.x;
    const int warp  = t >> 5, lane = t & 31;

    __shared__ float s_acc[8][REP][HD];   // 16 KB
    __shared__ float s_m[8], s_l[8][REP], s_alpha[8];
    __shared__ float s_ML[1 + REP];

    const float scale = 0.08838834764831845f;  // 1/sqrt(128)

    float4 qr[REP];
    #pragma unroll
    for (int r = 0; r < REP; r++) {
        const float* qp = qkv + (size_t)b * NQKV + (g * REP + r) * HD + lane * 4;
        float4 v = *(const float4*)qp;
        qr[r] = make_float4(v.x * scale, v.y * scale, v.z * scale, v.w * scale);
    }
    const float* knew = qkv + (size_t)b * NQKV + 4096 + g * HD;
    const float* vnew = qkv + (size_t)b * NQKV + 5120 + g * HD;

    float m = -1e30f;
    float l0 = 0.f, l1 = 0.f, l2 = 0.f, l3 = 0.f;
    float4 oa[REP];
    #pragma unroll
    for (int r = 0; r < REP; r++) oa[r] = make_float4(0.f, 0.f, 0.f, 0.f);

    const int tbase = split * CHUNK + warp * PPW;
    const size_t cbase = ((size_t)b * MAXS * HKV + g) * HD + lane * 4;

    // iteration-0 pointers
    const float* kp = (tbase < STARTP) ? kc + cbase + (size_t)tbase * (HKV * HD) : knew + lane * 4;
    const float* vp = (tbase < STARTP) ? vc + cbase + (size_t)tbase * (HKV * HD) : vnew + lane * 4;
    float4 kv = *(const float4*)kp;
    float4 vv = *(const float4*)vp;

    #pragma unroll
    for (int i = 0; i < PPW; i++) {
        float4 kn, vn;
        if (i + 1 < PPW) {                 // prefetch next position
            int tp = tbase + i + 1;
            const float* kp1 = (tp < STARTP) ? kc + cbase + (size_t)tp * (HKV * HD) : knew + lane * 4;
            const float* vp1 = (tp < STARTP) ? vc + cbase + (size_t)tp * (HKV * HD) : vnew + lane * 4;
            kn = *(const float4*)kp1;
            vn = *(const float4*)vp1;
        }

        float sc0 = kv.x*qr[0].x + kv.y*qr[0].y + kv.z*qr[0].z + kv.w*qr[0].w;
        float sc1 = kv.x*qr[1].x + kv.y*qr[1].y + kv.z*qr[1].z + kv.w*qr[1].w;
        float sc2 = kv.x*qr[2].x + kv.y*qr[2].y + kv.z*qr[2].z + kv.w*qr[2].w;
        float sc3 = kv.x*qr[3].x + kv.y*qr[3].y + kv.z*qr[3].z + kv.w*qr[3].w;
        #pragma unroll
        for (int off = 16; off > 0; off >>= 1) {
            sc0 += __shfl_xor_sync(0xffffffffu, sc0, off);
            sc1 += __shfl_xor_sync(0xffffffffu, sc1, off);
            sc2 += __shfl_xor_sync(0xffffffffu, sc2, off);
            sc3 += __shfl_xor_sync(0xffffffffu, sc3, off);
        }
        float mnew = fmaxf(fmaxf(fmaxf(sc0, sc1), fmaxf(sc2, sc3)), m);
        float corr = __expf(m - mnew);
        float p0 = __expf(sc0 - mnew);
        float p1 = __expf(sc1 - mnew);
        float p2 = __expf(sc2 - mnew);
        float p3 = __expf(sc3 - mnew);
        l0 = l0 * corr + p0;
        l1 = l1 * corr + p1;
        l2 = l2 * corr + p2;
        l3 = l3 * corr + p3;
        oa[0].x = oa[0].x*corr + p0*vv.x; oa[0].y = oa[0].y*corr + p0*vv.y;
        oa[0].z = oa[0].z*corr + p0*vv.z; oa[0].w = oa[0].w*corr + p0*vv.w;
        oa[1].x = oa[1].x*corr + p1*vv.x; oa[1].y = oa[1].y*corr + p1*vv.y;
        oa[1].z = oa[1].z*corr + p1*vv.z; oa[1].w = oa[1].w*corr + p1*vv.w;
        oa[2].x = oa[2].x*corr + p2*vv.x; oa[2].y = oa[2].y*corr + p2*vv.y;
        oa[2].z = oa[2].z*corr + p2*vv.z; oa[2].w = oa[2].w*corr + p2*vv.w;
        oa[3].x = oa[3].x*corr + p3*vv.x; oa[3].y = oa[3].y*corr + p3*vv.y;
        oa[3].z = oa[3].z*corr + p3*vv.z; oa[3].w = oa[3].w*corr + p3*vv.w;
        m = mnew;
        kv = kn; vv = vn;
    }

    if (lane == 0) {
        s_m[warp] = m;
        s_l[warp][0] = l0; s_l[warp][1] = l1;
        s_l[warp][2] = l2; s_l[warp][3] = l3;
    }
    #pragma unroll
    for (int r = 0; r < REP; r++)
        *(float4*)&s_acc[warp][r][lane * 4] = oa[r];
    __syncthreads();

    if (t == 0) {
        float M = s_m[0];
        #pragma unroll
        for (int w = 1; w < 8; w++) M = fmaxf(M, s_m[w]);
        float L[REP] = {0.f, 0.f, 0.f, 0.f};
        #pragma unroll
        for (int w = 0; w < 8; w++) {
            float a = __expf(s_m[w] - M);
            s_alpha[w] = a;
            #pragma unroll
            for (int r = 0; r < REP; r++) L[r] += a * s_l[w][r];
        }
        s_ML[0] = M;
        #pragma unroll
        for (int r = 0; r < REP; r++) s_ML[1 + r] = L[r];
    }
    __syncthreads();

    const size_t base = ((size_t)(b * HKV + g) * NSPLIT + split) * (REP * HD);
    for (int o = t; o < REP * HD; o += 256) {
        int r = o >> 7, d = o & (HD - 1);
        float sum = 0.f;
        #pragma unroll
        for (int w = 0; w < 8; w++) sum += s_alpha[w] * s_acc[w][r][d];
        pacc[base + o] = sum;
    }
    if (t < 1 + REP) {
        size_t mlb = ((size_t)(b * HKV + g) * NSPLIT + split) * 5;
        pml[mlb + t] = s_ML[t];
    }
}

// ---------------- combine KV splits into the final attention output ---------------
// grid: (HKV, B), block 256.  Preamble parallelized across 16 lanes.
__global__ __launch_bounds__(256) void attn_reduce(
    const float* __restrict__ pacc,
    const float* __restrict__ pml,
    float* __restrict__ attn)
{
    const int g = blockIdx.x, b = blockIdx.y;
    const int t = threadIdx.x;
    __shared__ float alpha[NSPLIT];
    __shared__ float s_inv[REP];

    const int bg = b * HKV + g;
    if (t < NSPLIT) {
        const float* ml = pml + ((size_t)bg * NSPLIT + t) * 5;
        float m  = ml[0];
        float v0 = ml[1], v1 = ml[2], v2 = ml[3], v3 = ml[4];
        float M = m;
        #pragma unroll
        for (int off = 8; off > 0; off >>= 1)
            M = fmaxf(M, __shfl_xor_sync(0xffffu, M, off));
        float a = __expf(m - M);
        alpha[t] = a;
        float L0 = a * v0, L1 = a * v1, L2 = a * v2, L3 = a * v3;
        #pragma unroll
        for (int off = 8; off > 0; off >>= 1) {
            L0 += __shfl_xor_sync(0xffffu, L0, off);
            L1 += __shfl_xor_sync(0xffffu, L1, off);
            L2 += __shfl_xor_sync(0xffffu, L2, off);
            L3 += __shfl_xor_sync(0xffffu, L3, off);
        }
        if (t == 0) {
            s_inv[0] = 1.0f / L0; s_inv[1] = 1.0f / L1;
            s_inv[2] = 1.0f / L2; s_inv[3] = 1.0f / L3;
        }
    }
    __syncthreads();

    for (int o = t; o < REP * HD; o += 256) {
        int r = o >> 7;
        float sum = 0.f;
        #pragma unroll
        for (int i = 0; i < NSPLIT; i++)
            sum += alpha[i] * pacc[((size_t)bg * NSPLIT + i) * (REP * HD) + o];
        attn[(size_t)b * (HQ * HD) + g * (REP * HD) + o] = sum * s_inv[r];
    }
}

// ---------------- sum split-K partials of the output projection -------------------
__global__ __launch_bounds__(256) void reduce_out(
    const float* __restrict__ part, float* __restrict__ out, int total)
{
    int idx = blockIdx.x * 256 + threadIdx.x;
    if (idx >= total) return;
    float a = part[idx];
    #pragma unroll 8
    for (int s = 1; s < KSPLIT; s++) a += part[(size_t)s * total + idx];
    out[idx] = a;
}

// ------------------------------------ launch --------------------------------------
extern "C" void kernel_launch(void* const* d_in, const int* in_sizes, int n_in,
                              void* d_out, int out_size)
{
    const float* x  = (const float*)d_in[0];
    const float* fc = (const float*)d_in[1];
    const float* fs = (const float*)d_in[2];
    const float* wq = (const float*)d_in[3];
    const float* wk = (const float*)d_in[4];
    const float* wv = (const float*)d_in[5];
    const float* wo = (const float*)d_in[6];
    const float* kc = (const float*)d_in[7];
    const float* vc = (const float*)d_in[8];
    float* out = (float*)d_out;

    void *p1, *pqkv, *pacc, *pml, *pattn, *p2;
    cudaGetSymbolAddress(&p1,   g_p1);
    cudaGetSymbolAddress(&pqkv, g_qkv);
    cudaGetSymbolAddress(&pacc, g_pacc);
    cudaGetSymbolAddress(&pml,  g_pml);
    cudaGetSymbolAddress(&pattn,g_attn);
    cudaGetSymbolAddress(&p2,   g_p2);

    // 1) fused QKV projection, split-K (grid 12 x 32 = 384 blocks)
    gemm_f32x2<<<dim3(NQKV / NT, KSPLIT), 256>>>(
        x, wq, wk, wv, (float*)p1, NQKV, DIM, DIM / KSPLIT);

    // 2) reduce partials + RoPE
    reduce_rope<<<(BB * (NQKV / 2) + 255) / 256, 256>>>(
        (const float*)p1, (float*)pqkv, fc, fs);

    // 3) flash-decode attention over KV splits
    attn_kernel<<<dim3(NSPLIT, HKV, BB), 256>>>(
        (const float*)pqkv, kc, vc, (float*)pacc, (float*)pml);

    // 4) combine splits
    attn_reduce<<<dim3(HKV, BB), 256>>>(
        (const float*)pacc, (const float*)pml, (float*)pattn);

    // 5) output projection, split-K (grid 8 x 32 = 256 blocks)
    gemm_f32x2<<<dim3(DIM / NT, KSPLIT), 256>>>(
        (const float*)pattn, wo, wo, wo, (float*)p2, DIM, HQ * HD, (HQ * HD) / KSPLIT);

    // 6) reduce into d_out
    reduce_out<<<(BB * DIM + 255) / 256, 256>>>((const float*)p2, out, BB * DIM);
}